// round 5
// baseline (speedup 1.0000x reference)
#include <cuda_runtime.h>
#include <cstddef>

#define CIN 128
#define HH  112
#define WW  112
#define OHH 56
#define OWW 56
#define NB  8

typedef unsigned long long ull;

__device__ __forceinline__ ull pack2(float a, float b) {
    ull r; asm("mov.b64 %0, {%1, %2};" : "=l"(r) : "f"(a), "f"(b)); return r;
}
__device__ __forceinline__ void unpack2(ull v, float& a, float& b) {
    asm("mov.b64 {%0, %1}, %2;" : "=f"(a), "=f"(b) : "l"(v));
}
__device__ __forceinline__ void ffma2(ull& acc, ull x, ull w) {
    asm("fma.rn.f32x2 %0, %1, %2, %0;" : "+l"(acc) : "l"(x), "l"(w));
}

// normalized sigma scratch: (8, 9, 56, 56) f32 = 3.6 MB
__device__ float g_sigma[(size_t)NB * 9 * OHH * OWW];

// ---------------------------------------------------------------------------
// Kernel 1: sigma at strided positions.
// CTA = 8x8 output tile. 256 thr = 8 warps; warp w owns channels 16w..16w+15,
// lanes = 32 position-pairs (8 oh x 4 ow-pairs). Weight LDS is warp-broadcast.
// f32x2 packed FMA over sc-pairs.
// smem: ws[128][9][12]=13824f, part[8][592]=4736f, red 576f, pad -> 76,672 B
// ---------------------------------------------------------------------------
#define WS_F   13824
#define PART_F 4736
#define PART_STRIDE 592
#define SM1_F  (WS_F + PART_F + 576 + 16)

__global__ void __launch_bounds__(256)
pasa_sigma_kernel(const float* __restrict__ x,
                  const float* __restrict__ cw,
                  const float* __restrict__ bnw,
                  const float* __restrict__ bnb,
                  const float* __restrict__ bnm,
                  const float* __restrict__ bnv)
{
    extern __shared__ float sm[];
    float* ws   = sm;                    // [c][tap][12] (sc contiguous, pad 3)
    float* part = sm + WS_F;             // [8 warp][592]
    float* red  = part + PART_F;         // [576]

    const int n   = blockIdx.y;
    const int t   = blockIdx.x;               // 0..48
    const int oh0 = (t / 7) * 8;
    const int ow0 = (t - (t / 7) * 7) * 8;
    const int tid = threadIdx.x;

    // stage weights: cw[sc][c][tap] -> ws[c*108 + tap*12 + sc]
    for (int i = tid; i < 10368; i += 256) {
        int sc  = i / 1152;
        int r   = i - sc * 1152;
        int c   = r / 9;
        int tap = r - c * 9;
        ws[c * 108 + tap * 12 + sc] = cw[i];
    }
    __syncthreads();

    const int w    = tid >> 5;           // warp = channel group (16 ch)
    const int lane = tid & 31;
    const int ohl  = lane >> 2;          // 0..7
    const int owg  = lane & 3;           // 0..3 -> ow pair (2*owg, 2*owg+1)
    const int oh   = oh0 + ohl;

    // input coords: rows 2*oh-1..+1 (reflect at -1), cols iwb..iwb+4
    int ihs[3];
#pragma unroll
    for (int r = 0; r < 3; ++r) { int v = 2 * oh - 1 + r; ihs[r] = v < 0 ? -v : v; }
    const int iwb  = 2 * ow0 + 4 * owg - 1;          // may be -1
    const int iws0 = iwb < 0 ? 1 : iwb;              // reflected scalar col
    const int iwv  = iwb + 1;                        // float4 col (mult of 4)

    const float* xn = x + (size_t)n * CIN * HH * WW + (size_t)(w * 16) * HH * WW;

    // accumulators: 2 positions x (4 sc-pairs + 1 scalar)
    ull  a01 = 0, a23 = 0, a45 = 0, a67 = 0;  float a8 = 0.f;
    ull  b01 = 0, b23 = 0, b45 = 0, b67 = 0;  float b8 = 0.f;

#pragma unroll 2
    for (int cc = 0; cc < 16; ++cc) {
        const float* xc = xn + (size_t)cc * HH * WW;
        float xv[3][5];
#pragma unroll
        for (int r = 0; r < 3; ++r) {
            const float* xr = xc + ihs[r] * WW;
            xv[r][0] = __ldg(xr + iws0);
            const float4 v4 = *(const float4*)(xr + iwv);
            xv[r][1] = v4.x; xv[r][2] = v4.y; xv[r][3] = v4.z; xv[r][4] = v4.w;
        }
        const float* wc = ws + (w * 16 + cc) * 108;
#pragma unroll
        for (int r = 0; r < 3; ++r) {
#pragma unroll
            for (int j = 0; j < 3; ++j) {
                const float* wt = wc + (r * 3 + j) * 12;
                const ull* wp = (const ull*)wt;
                const ull w01 = wp[0], w23 = wp[1], w45 = wp[2], w67 = wp[3];
                const float w8 = wt[8];
                const float xa = xv[r][j];
                const float xb = xv[r][j + 2];
                const ull xda = pack2(xa, xa);
                const ull xdb = pack2(xb, xb);
                ffma2(a01, xda, w01); ffma2(a23, xda, w23);
                ffma2(a45, xda, w45); ffma2(a67, xda, w67);
                a8 += xa * w8;
                ffma2(b01, xdb, w01); ffma2(b23, xdb, w23);
                ffma2(b45, xdb, w45); ffma2(b67, xdb, w67);
                b8 += xb * w8;
            }
        }
    }

    // spill partials: part[w][pos*9 + sc]
    {
        float s[9];
        unpack2(a01, s[0], s[1]); unpack2(a23, s[2], s[3]);
        unpack2(a45, s[4], s[5]); unpack2(a67, s[6], s[7]); s[8] = a8;
        float* pa = part + w * PART_STRIDE + (ohl * 8 + 2 * owg) * 9;
#pragma unroll
        for (int sc = 0; sc < 9; ++sc) pa[sc] = s[sc];
        unpack2(b01, s[0], s[1]); unpack2(b23, s[2], s[3]);
        unpack2(b45, s[4], s[5]); unpack2(b67, s[6], s[7]); s[8] = b8;
        float* pb = pa + 9;
#pragma unroll
        for (int sc = 0; sc < 9; ++sc) pb[sc] = s[sc];
    }
    __syncthreads();

    // reduce 8 warps, BN, clamp -> red[pos*9+sc]
    for (int i = tid; i < 576; i += 256) {
        float ssum = 0.f;
#pragma unroll
        for (int g = 0; g < 8; ++g) ssum += part[g * PART_STRIDE + i];
        const int sc = i % 9;
        const float scl = __ldg(bnw + sc) * rsqrtf(__ldg(bnv + sc) + 1e-5f);
        const float sh  = __ldg(bnb + sc) - __ldg(bnm + sc) * scl;
        red[i] = fmaxf(ssum * scl + sh, 1e-4f);
    }
    __syncthreads();

    // normalize per position, write sigma[n][sc][oh][ow]
    if (tid < 64) {
        const int pos = tid;
        float s = 0.f;
#pragma unroll
        for (int sc = 0; sc < 9; ++sc) s += red[pos * 9 + sc];
        const float inv = 1.f / s;
        const int oy = oh0 + (pos >> 3);
        const int ox = ow0 + (pos & 7);
        float* sg = g_sigma + ((size_t)n * 9 * OHH + oy) * OWW + ox;
#pragma unroll
        for (int sc = 0; sc < 9; ++sc)
            sg[(size_t)sc * OHH * OWW] = red[pos * 9 + sc] * inv;
    }
}

// ---------------------------------------------------------------------------
// Kernel 2: apply sigma. Thread = 4 consecutive ow of one (n,c,oh).
// block 224 = 16 oh-rows x 14 ow-groups; grid (4, 128, 8), oh guarded.
// ---------------------------------------------------------------------------
__global__ void __launch_bounds__(224)
pasa_apply_kernel(const float* __restrict__ x, float* __restrict__ out)
{
    const int n   = blockIdx.z;
    const int c   = blockIdx.y;
    const int tid = threadIdx.x;
    const int r   = tid / 14;
    const int owg = tid - r * 14;
    const int oh  = blockIdx.x * 16 + r;
    if (oh >= OHH) return;
    const int ow0 = owg * 4;

    const float* xc = x + ((size_t)(n * CIN + c)) * HH * WW;
    const int iwb  = 8 * owg - 1;                 // -1 only when owg==0
    const int iws0 = iwb < 0 ? 1 : iwb;
    const int iwv  = iwb + 1;                     // multiple of 8 -> aligned

    // load 3 rows x 9 consecutive cols
    float xr[3][9];
#pragma unroll
    for (int i = 0; i < 3; ++i) {
        int ih = 2 * oh - 1 + i; ih = ih < 0 ? -ih : ih;
        const float* row = xc + ih * WW;
        xr[i][0] = __ldg(row + iws0);
        const float4 va = *(const float4*)(row + iwv);
        const float4 vb = *(const float4*)(row + iwv + 4);
        xr[i][1] = va.x; xr[i][2] = va.y; xr[i][3] = va.z; xr[i][4] = va.w;
        xr[i][5] = vb.x; xr[i][6] = vb.y; xr[i][7] = vb.z; xr[i][8] = vb.w;
    }

    const float* sg = g_sigma + ((size_t)n * 9 * OHH + oh) * OWW + ow0;
    float o0 = 0.f, o1 = 0.f, o2 = 0.f, o3 = 0.f;
#pragma unroll
    for (int i = 0; i < 3; ++i) {
#pragma unroll
        for (int j = 0; j < 3; ++j) {
            const float4 s4 = *(const float4*)(sg + (size_t)(i * 3 + j) * OHH * OWW);
            o0 += xr[i][j]     * s4.x;
            o1 += xr[i][j + 2] * s4.y;
            o2 += xr[i][j + 4] * s4.z;
            o3 += xr[i][j + 6] * s4.w;
        }
    }
    float4 o = make_float4(o0, o1, o2, o3);
    *(float4*)(out + ((size_t)(n * CIN + c) * OHH + oh) * OWW + ow0) = o;
}

extern "C" void kernel_launch(void* const* d_in, const int* in_sizes, int n_in,
                              void* d_out, int out_size)
{
    const float* x   = (const float*)d_in[0];
    const float* cw  = (const float*)d_in[1];
    const float* bnw = (const float*)d_in[2];
    const float* bnb = (const float*)d_in[3];
    const float* bnm = (const float*)d_in[4];
    const float* bnv = (const float*)d_in[5];
    float* out = (float*)d_out;

    const int smem1 = SM1_F * sizeof(float);
    cudaFuncSetAttribute(pasa_sigma_kernel,
                         cudaFuncAttributeMaxDynamicSharedMemorySize, smem1);

    dim3 g1(49, NB, 1);
    pasa_sigma_kernel<<<g1, 256, smem1>>>(x, cw, bnw, bnb, bnm, bnv);

    dim3 g2(4, CIN, NB);
    pasa_apply_kernel<<<g2, 224>>>(x, out);
}

// round 6
// speedup vs baseline: 1.3161x; 1.3161x over previous
#include <cuda_runtime.h>
#include <cstddef>

#define CIN 128
#define HH  112
#define WW  112
#define OHH 56
#define OWW 56
#define NB  8

typedef unsigned long long ull;
__device__ __forceinline__ ull pack2(float a, float b) {
    ull r; asm("mov.b64 %0, {%1, %2};" : "=l"(r) : "f"(a), "f"(b)); return r;
}
__device__ __forceinline__ void unpack2(ull v, float& a, float& b) {
    asm("mov.b64 {%0, %1}, %2;" : "=f"(a), "=f"(b) : "l"(v));
}
__device__ __forceinline__ void ffma2(ull& acc, ull x, ull w) {
    asm("fma.rn.f32x2 %0, %1, %2, %0;" : "+l"(acc) : "l"(x), "l"(w));
}

__device__ float g_sigma[(size_t)NB * 9 * OHH * OWW];  // (8,9,56,56)

// K1: CTA = 8x8 tile. Double-buffered 16-ch x 17x17 smem staging + f32x2 FMA.
// smem: buf[2][16][17][20]=10880f, ws[128][9][10]=11520f (aliased by part/red).
#define BUFB_F 5440
#define BUF_F  10880
#define SM1_F  22400
#define PSTR   592
#define CHEL   4624

__global__ void __launch_bounds__(256, 2)
pasa_sigma_kernel(const float* __restrict__ x, const float* __restrict__ cw,
                  const float* __restrict__ bnw, const float* __restrict__ bnb,
                  const float* __restrict__ bnm, const float* __restrict__ bnv)
{
    extern __shared__ float sm[];
    float* buf  = sm;
    float* ws   = sm + BUF_F;       // [c][tap][10]
    float* part = ws;               // alias after phase A: [8][592]
    float* red  = ws + 4736;        // [576]

    const int n   = blockIdx.y;
    const int t   = blockIdx.x;
    const int oh0 = (t / 7) * 8, ow0 = (t - (t / 7) * 7) * 8;
    const int tid = threadIdx.x;
    const int ihb = 2 * oh0 - 1, iwb = 2 * ow0 - 1;
    const float* xn = x + (size_t)n * CIN * HH * WW;

    for (int i = tid; i < 10368; i += 256) {
        float v = cw[i];
        int sc = i / 1152, r = i - sc * 1152, c = r / 9, tap = r - c * 9;
        ws[c * 90 + tap * 10 + sc] = v;
    }
    for (int i = tid; i < 1152; i += 256) ws[i * 10 + 9] = 0.f;

    // staging map: 19 elems/thread; pack goff(18b) | soff<<18
    int pk[19];
#pragma unroll
    for (int j = 0; j < 19; ++j) {
        int i = tid + j * 256;
        if (i < CHEL) {
            int cc = i / 289, s = i - cc * 289, r = s / 17, col = s - r * 17;
            int ih = ihb + r;  ih = ih < 0 ? -ih : ih;
            int iw = iwb + col; iw = iw < 0 ? -iw : iw;
            pk[j] = (cc * HH * WW + ih * WW + iw) | ((cc * 340 + r * 20 + col) << 18);
        } else pk[j] = (17 << 18);   // dummy -> pad slot
    }
#pragma unroll
    for (int j = 0; j < 19; ++j) buf[pk[j] >> 18] = __ldg(xn + (pk[j] & 0x3FFFF));
    __syncthreads();

    const int w = tid >> 5, lane = tid & 31;
    const int ohl = lane >> 2, owg = lane & 3;
    ull a01 = 0, a23 = 0, a45 = 0, a67 = 0;  float a8 = 0.f;
    ull b01 = 0, b23 = 0, b45 = 0, b67 = 0;  float b8 = 0.f;

    for (int k = 0; k < 8; ++k) {
        float pf[19];
        if (k < 7) {
            const float* xk = xn + (size_t)(k + 1) * 16 * HH * WW;
#pragma unroll
            for (int j = 0; j < 19; ++j) pf[j] = __ldg(xk + (pk[j] & 0x3FFFF));
        }
        const float* xb = buf + (k & 1) * BUFB_F;
#pragma unroll
        for (int ccs = 0; ccs < 2; ++ccs) {
            const int ccl = 2 * w + ccs;
            const float* xc = xb + ccl * 340 + 2 * ohl * 20 + 4 * owg;
            float xv[3][5];
#pragma unroll
            for (int dy = 0; dy < 3; ++dy) {
                const float4 v4 = *(const float4*)(xc + dy * 20);
                xv[dy][0] = v4.x; xv[dy][1] = v4.y; xv[dy][2] = v4.z;
                xv[dy][3] = v4.w; xv[dy][4] = xc[dy * 20 + 4];
            }
            const float* wc = ws + (k * 16 + ccl) * 90;
#pragma unroll
            for (int dy = 0; dy < 3; ++dy)
#pragma unroll
                for (int dx = 0; dx < 3; ++dx) {
                    const float* wt = wc + (dy * 3 + dx) * 10;
                    const ull* wp = (const ull*)wt;
                    const ull w01 = wp[0], w23 = wp[1], w45 = wp[2], w67 = wp[3];
                    const float w8 = wt[8];
                    const float xa = xv[dy][dx], xb2 = xv[dy][dx + 2];
                    const ull da = pack2(xa, xa), db = pack2(xb2, xb2);
                    ffma2(a01, da, w01); ffma2(a23, da, w23);
                    ffma2(a45, da, w45); ffma2(a67, da, w67); a8 += xa * w8;
                    ffma2(b01, db, w01); ffma2(b23, db, w23);
                    ffma2(b45, db, w45); ffma2(b67, db, w67); b8 += xb2 * w8;
                }
        }
        if (k < 7) {
            float* bo = buf + ((k + 1) & 1) * BUFB_F;
#pragma unroll
            for (int j = 0; j < 19; ++j) bo[pk[j] >> 18] = pf[j];
        }
        __syncthreads();
    }

    {
        float s[9];
        unpack2(a01, s[0], s[1]); unpack2(a23, s[2], s[3]);
        unpack2(a45, s[4], s[5]); unpack2(a67, s[6], s[7]); s[8] = a8;
        float* pa = part + w * PSTR + (ohl * 8 + 2 * owg) * 9;
#pragma unroll
        for (int sc = 0; sc < 9; ++sc) pa[sc] = s[sc];
        unpack2(b01, s[0], s[1]); unpack2(b23, s[2], s[3]);
        unpack2(b45, s[4], s[5]); unpack2(b67, s[6], s[7]); s[8] = b8;
#pragma unroll
        for (int sc = 0; sc < 9; ++sc) pa[9 + sc] = s[sc];
    }
    __syncthreads();

    for (int i = tid; i < 576; i += 256) {
        float ssum = 0.f;
#pragma unroll
        for (int g = 0; g < 8; ++g) ssum += part[g * PSTR + i];
        const int sc = i % 9;
        const float scl = __ldg(bnw + sc) * rsqrtf(__ldg(bnv + sc) + 1e-5f);
        red[i] = fmaxf(ssum * scl + (__ldg(bnb + sc) - __ldg(bnm + sc) * scl), 1e-4f);
    }
    __syncthreads();

    if (tid < 64) {
        float s = 0.f;
#pragma unroll
        for (int sc = 0; sc < 9; ++sc) s += red[tid * 9 + sc];
        const float inv = 1.f / s;
        float* sg = g_sigma + ((size_t)n * 9 * OHH + oh0 + (tid >> 3)) * OWW
                  + ow0 + (tid & 7);
#pragma unroll
        for (int sc = 0; sc < 9; ++sc)
            sg[(size_t)sc * OHH * OWW] = red[tid * 9 + sc] * inv;
    }
}

// K2: thread = 2 oh x 4 ow (8 outputs). 1568 blocks x 256.
__global__ void __launch_bounds__(256)
pasa_apply_kernel(const float* __restrict__ x, float* __restrict__ out)
{
    const int idx = blockIdx.x * 256 + threadIdx.x;
    const int owq = idx % 14;
    int r2 = idx / 14;
    const int ohp = r2 % 28;  r2 /= 28;
    const int c = r2 % 128, n = r2 / 128;
    const int oh = 2 * ohp, ow0 = 4 * owq;

    const float* xc = x + ((size_t)(n * CIN + c)) * HH * WW;
    const int iwb = 8 * owq - 1;
    const int iws0 = iwb < 0 ? 1 : iwb, iwv = iwb + 1;

    float xr[5][9];
#pragma unroll
    for (int i = 0; i < 5; ++i) {
        int ih = 4 * ohp - 1 + i; ih = ih < 0 ? -ih : ih;
        const float* row = xc + ih * WW;
        xr[i][0] = __ldg(row + iws0);
        const float4 va = *(const float4*)(row + iwv);
        const float4 vb = *(const float4*)(row + iwv + 4);
        xr[i][1] = va.x; xr[i][2] = va.y; xr[i][3] = va.z; xr[i][4] = va.w;
        xr[i][5] = vb.x; xr[i][6] = vb.y; xr[i][7] = vb.z; xr[i][8] = vb.w;
    }

    const float* sgA = g_sigma + ((size_t)n * 9 * OHH + oh) * OWW + ow0;
    float a0 = 0, a1 = 0, a2 = 0, a3 = 0, b0 = 0, b1 = 0, b2 = 0, b3 = 0;
#pragma unroll
    for (int i = 0; i < 3; ++i)
#pragma unroll
        for (int j = 0; j < 3; ++j) {
            const size_t toff = (size_t)(i * 3 + j) * OHH * OWW;
            const float4 sa = *(const float4*)(sgA + toff);
            a0 += xr[i][j] * sa.x;     a1 += xr[i][j + 2] * sa.y;
            a2 += xr[i][j + 4] * sa.z; a3 += xr[i][j + 6] * sa.w;
            const float4 sb = *(const float4*)(sgA + toff + OWW);
            b0 += xr[i + 2][j] * sb.x;     b1 += xr[i + 2][j + 2] * sb.y;
            b2 += xr[i + 2][j + 4] * sb.z; b3 += xr[i + 2][j + 6] * sb.w;
        }
    float* op = out + ((size_t)(n * CIN + c) * OHH + oh) * OWW + ow0;
    *(float4*)op         = make_float4(a0, a1, a2, a3);
    *(float4*)(op + OWW) = make_float4(b0, b1, b2, b3);
}

extern "C" void kernel_launch(void* const* d_in, const int* in_sizes, int n_in,
                              void* d_out, int out_size)
{
    const float* x   = (const float*)d_in[0];
    const float* cw  = (const float*)d_in[1];
    const float* bnw = (const float*)d_in[2];
    const float* bnb = (const float*)d_in[3];
    const float* bnm = (const float*)d_in[4];
    const float* bnv = (const float*)d_in[5];
    cudaFuncSetAttribute(pasa_sigma_kernel,
                         cudaFuncAttributeMaxDynamicSharedMemorySize,
                         SM1_F * sizeof(float));
    dim3 g1(49, NB, 1);
    pasa_sigma_kernel<<<g1, 256, SM1_F * sizeof(float)>>>(x, cw, bnw, bnb, bnm, bnv);
    pasa_apply_kernel<<<1568, 256>>>(x, (float*)d_out);
}

// round 8
// speedup vs baseline: 2.3447x; 1.7816x over previous
#include <cuda_runtime.h>
#include <cstddef>

#define CIN 128
#define HW  (112 * 112)
#define WWI 112
#define OWW 56

typedef unsigned long long ull;
__device__ __forceinline__ ull pack2(float a, float b) {
    ull r; asm("mov.b64 %0, {%1, %2};" : "=l"(r) : "f"(a), "f"(b)); return r;
}
__device__ __forceinline__ void unpack2(ull v, float& a, float& b) {
    asm("mov.b64 {%0, %1}, %2;" : "=f"(a), "=f"(b) : "l"(v));
}
__device__ __forceinline__ void ffma2(ull& acc, ull x, ull w) {
    asm("fma.rn.f32x2 %0, %1, %2, %0;" : "+l"(acc) : "l"(x), "l"(w));
}

// smem: ws[128][9][10]=11520f | part[8][512]=4096f | red[512]
#define WS_F   11520
#define PSTR   512
#define RED_O  (WS_F + 8 * PSTR)
#define SM_F   (RED_O + 512)          // 16128 f = 64512 B

__global__ void __launch_bounds__(256, 3)
pasa_fused_kernel(const float* __restrict__ x,  const float* __restrict__ cw,
                  const float* __restrict__ bnw, const float* __restrict__ bnb,
                  const float* __restrict__ bnm, const float* __restrict__ bnv,
                  float* __restrict__ out)
{
    extern __shared__ float sm[];
    float* ws   = sm;
    float* part = sm + WS_F;
    float* red  = sm + RED_O;

    const int oh  = blockIdx.x;          // 0..55
    const int n   = blockIdx.y;          // 0..7
    const int tid = threadIdx.x;
    const int w   = tid >> 5;            // warp -> channels 16w..16w+15
    const int lane = tid & 31;
    const int l    = lane < 28 ? lane : 27;   // clamped lane
    const bool act = lane < 28;

    // stage weights: cw[sc][c][tap] -> ws[c*90 + tap*10 + sc]
    for (int i = tid; i < 10368; i += 256) {
        float v = cw[i];
        int sc = i / 1152, r = i - sc * 1152, c = r / 9, tap = r - c * 9;
        ws[c * 90 + tap * 10 + sc] = v;
    }
    __syncthreads();

    int ihs[3];
#pragma unroll
    for (int d = 0; d < 3; ++d) { int v = 2 * oh - 1 + d; ihs[d] = v < 0 ? -v : v; }
    const float* xn = x + (size_t)n * CIN * HW + (size_t)(w * 16) * HW;
    const int cb = 4 * l;

    // ---------------- Phase A: sigma partials ----------------
    ull a01 = 0, a23 = 0, a45 = 0, a67 = 0;  float a8 = 0.f;
    ull b01 = 0, b23 = 0, b45 = 0, b67 = 0;  float b8 = 0.f;

    for (int cc = 0; cc < 16; ++cc) {
        const float* xc = xn + (size_t)cc * HW;
        float xv[3][5];
#pragma unroll
        for (int d = 0; d < 3; ++d) {
            const float4 v = *(const float4*)(xc + ihs[d] * WWI + cb);
            float left = __shfl_up_sync(0xffffffffu, v.w, 1);
            if (lane == 0) left = v.y;           // reflect col -1 -> col 1
            xv[d][0] = left; xv[d][1] = v.x; xv[d][2] = v.y;
            xv[d][3] = v.z;  xv[d][4] = v.w;
        }
        const float* wc = ws + (w * 16 + cc) * 90;
#pragma unroll
        for (int dy = 0; dy < 3; ++dy)
#pragma unroll
            for (int dx = 0; dx < 3; ++dx) {
                const float* wt = wc + (dy * 3 + dx) * 10;
                const ull* wp = (const ull*)wt;
                const ull w01 = wp[0], w23 = wp[1], w45 = wp[2], w67 = wp[3];
                const float w8 = wt[8];
                const float xa = xv[dy][dx], xb = xv[dy][dx + 2];
                const ull da = pack2(xa, xa), db = pack2(xb, xb);
                ffma2(a01, da, w01); ffma2(a23, da, w23);
                ffma2(a45, da, w45); ffma2(a67, da, w67); a8 += xa * w8;
                ffma2(b01, db, w01); ffma2(b23, db, w23);
                ffma2(b45, db, w45); ffma2(b67, db, w67); b8 += xb * w8;
            }
    }

    if (act) {
        float s[9];
        unpack2(a01, s[0], s[1]); unpack2(a23, s[2], s[3]);
        unpack2(a45, s[4], s[5]); unpack2(a67, s[6], s[7]); s[8] = a8;
        float* pa = part + w * PSTR + (2 * l) * 9;
#pragma unroll
        for (int sc = 0; sc < 9; ++sc) pa[sc] = s[sc];
        unpack2(b01, s[0], s[1]); unpack2(b23, s[2], s[3]);
        unpack2(b45, s[4], s[5]); unpack2(b67, s[6], s[7]); s[8] = b8;
#pragma unroll
        for (int sc = 0; sc < 9; ++sc) pa[9 + sc] = s[sc];
    }
    __syncthreads();

    // reduce over 8 warps + BN + clamp
    for (int i = tid; i < 504; i += 256) {
        float ssum = 0.f;
#pragma unroll
        for (int g = 0; g < 8; ++g) ssum += part[g * PSTR + i];
        const int sc = i % 9;
        const float scl = __ldg(bnw + sc) * rsqrtf(__ldg(bnv + sc) + 1e-5f);
        red[i] = fmaxf(ssum * scl + (__ldg(bnb + sc) - __ldg(bnm + sc) * scl), 1e-4f);
    }
    __syncthreads();
    // normalize per position
    if (tid < 56) {
        float s = 0.f;
#pragma unroll
        for (int sc = 0; sc < 9; ++sc) s += red[tid * 9 + sc];
        const float inv = 1.f / s;
#pragma unroll
        for (int sc = 0; sc < 9; ++sc) red[tid * 9 + sc] *= inv;
    }
    __syncthreads();

    // ---------------- Phase B: apply ----------------
    ull sp[9];
#pragma unroll
    for (int t = 0; t < 9; ++t)
        sp[t] = pack2(red[(2 * l) * 9 + t], red[(2 * l) * 9 + 9 + t]);

    float* on = out + ((size_t)(n * CIN + w * 16) * OWW + oh) * OWW + 2 * l;

    for (int cc = 0; cc < 16; ++cc) {
        const float* xc = xn + (size_t)cc * HW;
        ull acc = 0;
#pragma unroll
        for (int d = 0; d < 3; ++d) {
            const float4 v = *(const float4*)(xc + ihs[d] * WWI + cb);
            float left = __shfl_up_sync(0xffffffffu, v.w, 1);
            if (lane == 0) left = v.y;
            const float xv0 = left, xv1 = v.x, xv2 = v.y, xv3 = v.z, xv4 = v.w;
            ffma2(acc, pack2(xv0, xv2), sp[d * 3 + 0]);
            ffma2(acc, pack2(xv1, xv3), sp[d * 3 + 1]);
            ffma2(acc, pack2(xv2, xv4), sp[d * 3 + 2]);
        }
        if (act) {
            float oa, ob; unpack2(acc, oa, ob);
            *(float2*)(on + (size_t)cc * OWW * OWW) = make_float2(oa, ob);
        }
    }
}

extern "C" void kernel_launch(void* const* d_in, const int* in_sizes, int n_in,
                              void* d_out, int out_size)
{
    const float* x   = (const float*)d_in[0];
    const float* cw  = (const float*)d_in[1];
    const float* bnw = (const float*)d_in[2];
    const float* bnb = (const float*)d_in[3];
    const float* bnm = (const float*)d_in[4];
    const float* bnv = (const float*)d_in[5];
    cudaFuncSetAttribute(pasa_fused_kernel,
                         cudaFuncAttributeMaxDynamicSharedMemorySize,
                         SM_F * sizeof(float));
    dim3 grid(OWW, 8);
    pasa_fused_kernel<<<grid, 256, SM_F * sizeof(float)>>>(
        x, cw, bnw, bnb, bnm, bnv, (float*)d_out);
}